// round 4
// baseline (speedup 1.0000x reference)
#include <cuda_runtime.h>
#include <cuda_bf16.h>
#include <math.h>
#include <cstdint>

// ---------------------------------------------------------------------------
// Problem constants
// ---------------------------------------------------------------------------
#define BATCH 8
#define SV    257
#define SQ    2048
#define DV    1024
#define DM    2304
#define NH    8
#define DK    288
#define DF    9216
#define ROWS_T (BATCH*SQ)  // 16384
#define ROWS_V (BATCH*SV)  // 2056

// ---------------------------------------------------------------------------
// Scratch (device globals; no runtime allocation allowed)
// ---------------------------------------------------------------------------
__device__ float g_pv [(size_t)ROWS_V * DM];
__device__ float g_nt [(size_t)ROWS_T * DM];
__device__ float g_q  [(size_t)ROWS_T * DM];
__device__ float g_k  [(size_t)ROWS_V * DM];
__device__ float g_v  [(size_t)ROWS_V * DM];
__device__ float g_ctx[(size_t)ROWS_T * DM];
__device__ float g_x  [(size_t)ROWS_T * DM];
__device__ float g_h  [(size_t)ROWS_T * DF];

// ---------------------------------------------------------------------------
// helpers
// ---------------------------------------------------------------------------
__device__ __forceinline__ uint32_t smem_u32(const void* p) {
    uint32_t a;
    asm("{ .reg .u64 t; cvta.to.shared.u64 t, %1; cvt.u32.u64 %0, t; }"
        : "=r"(a) : "l"(p));
    return a;
}
__device__ __forceinline__ void cp16(uint32_t dst, const void* src, uint32_t n) {
    asm volatile("cp.async.cg.shared.global [%0], [%1], 16, %2;"
                 :: "r"(dst), "l"(src), "r"(n) : "memory");
}
__device__ __forceinline__ uint32_t f2tf(float x) {
    uint32_t r;
    asm("cvt.rna.tf32.f32 %0, %1;" : "=r"(r) : "f"(x));
    return r;
}
__device__ __forceinline__ void mma_tf32(float* c, const uint32_t* a,
                                         const uint32_t* b) {
    asm volatile(
        "mma.sync.aligned.m16n8k8.row.col.f32.tf32.tf32.f32 "
        "{%0,%1,%2,%3}, {%4,%5,%6,%7}, {%8,%9}, {%0,%1,%2,%3};"
        : "+f"(c[0]), "+f"(c[1]), "+f"(c[2]), "+f"(c[3])
        : "r"(a[0]), "r"(a[1]), "r"(a[2]), "r"(a[3]), "r"(b[0]), "r"(b[1]));
}
__device__ __forceinline__ float gelu_exact(float x) {
    return 0.5f * x * (1.0f + erff(x * 0.70710678118654752f));
}

// ---------------------------------------------------------------------------
// tf32 HMMA GEMM: C[M,N] = A[M,K] @ B[K,N] + bias (+ epilogue)
//   EPI 0: +bias   EPI 1: +bias+res   EPI 2: gelu(+bias)
// CTA tile 128x256, KC=32, 4-stage cp.async, 8 warps x (64x64) warp tiles,
// fragment double-buffering across k-steps.
// Requires: K % 32 == 0, N % 256 == 0, K/32 >= 3. M tail handled.
// ---------------------------------------------------------------------------
#define TM 128
#define TN 256
#define KC 32
#define NSTG 4
#define A_BYTES 16384                 // 128 x 32 x 4
#define STG_BYTES 49152               // A 16KB + B 32KB
#define GEMM_SMEM (NSTG * STG_BYTES)  // 196608

// A smem: row-major [128][32] floats, col swizz: c = (k + 4*(row&7)) & 31
// B smem: row-major [32][256] floats, col swizz: c = (n&~31) | ((n + 8*(k&3)) & 31)

__device__ __forceinline__ void load_stage(
    const float* __restrict__ A, const float* __restrict__ Bw,
    int M, int N, int K, uint32_t stg, int bm, int n0, int kc, int tid)
{
#pragma unroll
    for (int i = 0; i < 4; i++) {            // A: 1024 cp16 / 256 thr
        const int ai = tid + i * 256;
        const int row = ai >> 3, c4 = ai & 7;
        const uint32_t col = (uint32_t)((c4 * 4 + 4 * (row & 7)) & 31);
        const uint32_t dst = stg + row * 128 + col * 4;
        const int gr = bm + row;
        const int ok = gr < M;
        const float* src = A + (size_t)(ok ? gr : 0) * K + kc + c4 * 4;
        cp16(dst, src, ok ? 16u : 0u);
    }
#pragma unroll
    for (int i = 0; i < 8; i++) {            // B: 2048 cp16 / 256 thr
        const int bi = tid + i * 256;
        const int k = bi >> 6, c4 = bi & 63;
        const int n = c4 * 4;
        const uint32_t col = (uint32_t)((n & ~31) | ((n + 8 * (k & 3)) & 31));
        const uint32_t dst = stg + A_BYTES + k * 1024 + col * 4;
        const float* src = Bw + (size_t)(kc + k) * N + n0 + n;
        cp16(dst, src, 16u);
    }
}

__device__ __forceinline__ void load_frags(
    const float* __restrict__ As, const float* __restrict__ Bs,
    int ks, int lk, int l4, int wm, int wn,
    uint32_t* __restrict__ a, uint32_t* __restrict__ b)
{
    const int k0 = ks * 8 + lk;
    const int k1 = k0 + 4;
#pragma unroll
    for (int mt = 0; mt < 4; mt++) {
        const int r0 = wm + mt * 16 + l4;
        const int r1 = r0 + 8;
        a[mt * 4 + 0] = f2tf(As[r0 * 32 + ((k0 + 4 * (r0 & 7)) & 31)]);
        a[mt * 4 + 1] = f2tf(As[r1 * 32 + ((k0 + 4 * (r1 & 7)) & 31)]);
        a[mt * 4 + 2] = f2tf(As[r0 * 32 + ((k1 + 4 * (r0 & 7)) & 31)]);
        a[mt * 4 + 3] = f2tf(As[r1 * 32 + ((k1 + 4 * (r1 & 7)) & 31)]);
    }
#pragma unroll
    for (int nt = 0; nt < 8; nt++) {
        const int n = wn + nt * 8 + l4;
        const int sw = n & ~31;
        b[nt * 2 + 0] = f2tf(Bs[k0 * 256 + (sw | ((n + 8 * (k0 & 3)) & 31))]);
        b[nt * 2 + 1] = f2tf(Bs[k1 * 256 + (sw | ((n + 8 * (k1 & 3)) & 31))]);
    }
}

template <int EPI>
__global__ void __launch_bounds__(256, 1)
tgemm(const float* __restrict__ A, const float* __restrict__ Bw,
      const float* __restrict__ bias, const float* __restrict__ res,
      float* __restrict__ C, int M, int N, int K)
{
    extern __shared__ char smem[];
    const uint32_t sb = smem_u32(smem);
    const int tid  = threadIdx.x;
    const int lane = tid & 31;
    const int wid  = tid >> 5;
    const int wm   = (wid >> 2) * 64;     // warp row offset (0, 64)
    const int wn   = (wid & 3) * 64;      // warp col offset (0..192)
    const int bm   = blockIdx.y * TM;
    const int n0   = blockIdx.x * TN;
    const int nch  = K / KC;

    float c[4][8][4];
#pragma unroll
    for (int mt = 0; mt < 4; mt++)
#pragma unroll
        for (int nt = 0; nt < 8; nt++)
#pragma unroll
            for (int r = 0; r < 4; r++) c[mt][nt][r] = 0.f;

    // prologue: stages 0,1,2 (nch >= 3 at all call sites)
#pragma unroll
    for (int p = 0; p < 3; p++) {
        load_stage(A, Bw, M, N, K, sb + p * STG_BYTES, bm, n0, p * KC, tid);
        asm volatile("cp.async.commit_group;" ::: "memory");
    }

    const int l4 = lane >> 2;      // 0..7
    const int lk = lane & 3;       // 0..3

    uint32_t af[2][16], bf[2][16];

    for (int chunk = 0; chunk < nch; ++chunk) {
        asm volatile("cp.async.wait_group 2;" ::: "memory");
        __syncthreads();

        // issue next-chunk loads early (overlap with math below)
        const int nx = chunk + 3;
        if (nx < nch)
            load_stage(A, Bw, M, N, K, sb + (nx & (NSTG - 1)) * STG_BYTES,
                       bm, n0, nx * KC, tid);
        asm volatile("cp.async.commit_group;" ::: "memory");

        const char* stage = smem + (chunk & (NSTG - 1)) * STG_BYTES;
        const float* As = (const float*)stage;
        const float* Bs = (const float*)(stage + A_BYTES);

        load_frags(As, Bs, 0, lk, l4, wm, wn, af[0], bf[0]);
#pragma unroll
        for (int ks = 0; ks < 4; ks++) {
            const int cur = ks & 1;
            if (ks < 3)
                load_frags(As, Bs, ks + 1, lk, l4, wm, wn,
                           af[cur ^ 1], bf[cur ^ 1]);
#pragma unroll
            for (int mt = 0; mt < 4; mt++)
#pragma unroll
                for (int nt = 0; nt < 8; nt++)
                    mma_tf32(c[mt][nt], &af[cur][mt * 4], &bf[cur][nt * 2]);
        }
    }

    // -------- epilogue --------
#pragma unroll
    for (int mt = 0; mt < 4; mt++) {
        const int rb = bm + wm + mt * 16 + l4;
#pragma unroll
        for (int hh = 0; hh < 2; hh++) {
            const int row = rb + hh * 8;
            if (row < M) {
#pragma unroll
                for (int nt = 0; nt < 8; nt++) {
                    const int col = n0 + wn + nt * 8 + lk * 2;
                    float v0 = c[mt][nt][hh * 2 + 0] + bias[col];
                    float v1 = c[mt][nt][hh * 2 + 1] + bias[col + 1];
                    if (EPI == 1) {
                        const float2 r2 = *(const float2*)&res[(size_t)row * N + col];
                        v0 += r2.x; v1 += r2.y;
                    } else if (EPI == 2) {
                        v0 = gelu_exact(v0); v1 = gelu_exact(v1);
                    }
                    *(float2*)&C[(size_t)row * N + col] = make_float2(v0, v1);
                }
            }
        }
    }
}

// ---------------------------------------------------------------------------
// LayerNorm over last dim (C = DM), one block per row
// ---------------------------------------------------------------------------
__global__ void __launch_bounds__(256)
layernorm_kernel(const float* __restrict__ x, const float* __restrict__ w,
                 const float* __restrict__ bta, float* __restrict__ y, int C)
{
    const size_t base = (size_t)blockIdx.x * C;
    float s = 0.f, s2 = 0.f;
    for (int c = threadIdx.x; c < C; c += 256) {
        const float v = x[base + c];
        s += v; s2 += v * v;
    }
#pragma unroll
    for (int o = 16; o; o >>= 1) {
        s  += __shfl_xor_sync(0xffffffffu, s,  o);
        s2 += __shfl_xor_sync(0xffffffffu, s2, o);
    }
    __shared__ float sh[16];
    __shared__ float mv[2];
    const int wid = threadIdx.x >> 5, lane = threadIdx.x & 31;
    if (lane == 0) { sh[wid] = s; sh[8 + wid] = s2; }
    __syncthreads();
    if (threadIdx.x == 0) {
        float ts = 0.f, ts2 = 0.f;
#pragma unroll
        for (int i = 0; i < 8; i++) { ts += sh[i]; ts2 += sh[8 + i]; }
        const float mean = ts / (float)C;
        const float var  = ts2 / (float)C - mean * mean;
        mv[0] = mean;
        mv[1] = rsqrtf(var + 1e-5f);
    }
    __syncthreads();
    const float mean = mv[0], rstd = mv[1];
    for (int c = threadIdx.x; c < C; c += 256)
        y[base + c] = (x[base + c] - mean) * rstd * w[c] + bta[c];
}

// ---------------------------------------------------------------------------
// Cross attention (fp32) — unchanged (passing)
// ---------------------------------------------------------------------------
#define ATT_TQ 32
#define ATT_KC 32
#define SVP    260
#define ATT_SMEM ((ATT_TQ*DK + ATT_TQ*SVP + ATT_KC*DK) * (int)sizeof(float))

__global__ void __launch_bounds__(256)
attention_kernel(const float* __restrict__ Q, const float* __restrict__ Km,
                 const float* __restrict__ Vm, float* __restrict__ O)
{
    extern __shared__ float sm[];
    float* qs = sm;
    float* ss = qs + ATT_TQ * DK;
    float* kv = ss + ATT_TQ * SVP;

    const int q0   = blockIdx.x * ATT_TQ;
    const int b    = blockIdx.y / NH;
    const int h    = blockIdx.y % NH;
    const int tid  = threadIdx.x;
    const int lane = tid & 31;
    const int w    = tid >> 5;
    const float scale = 0.05892556509887896f;   // 1/sqrt(288)

    const float* qg = Q + ((size_t)(b * SQ + q0)) * DM + h * DK;
    for (int idx = tid; idx < ATT_TQ * DK; idx += 256) {
        const int r = idx / DK, c = idx - r * DK;
        qs[idx] = qg[(size_t)r * DM + c];
    }
    __syncthreads();

    float qr[4][9];
#pragma unroll
    for (int i = 0; i < 4; i++)
#pragma unroll
        for (int t = 0; t < 9; t++)
            qr[i][t] = qs[(w * 4 + i) * DK + lane + t * 32];

    const float* kg = Km + ((size_t)(b * SV)) * DM + h * DK;
    for (int j0 = 0; j0 < SV; j0 += ATT_KC) {
        const int jn = min(ATT_KC, SV - j0);
        for (int idx = tid; idx < jn * DK; idx += 256) {
            const int r = idx / DK, c = idx - r * DK;
            kv[idx] = kg[(size_t)(j0 + r) * DM + c];
        }
        __syncthreads();
        for (int j = 0; j < jn; j++) {
            float a0 = 0.f, a1 = 0.f, a2 = 0.f, a3 = 0.f;
#pragma unroll
            for (int t = 0; t < 9; t++) {
                const float kvv = kv[j * DK + lane + t * 32];
                a0 += qr[0][t] * kvv;  a1 += qr[1][t] * kvv;
                a2 += qr[2][t] * kvv;  a3 += qr[3][t] * kvv;
            }
#pragma unroll
            for (int o = 16; o; o >>= 1) {
                a0 += __shfl_xor_sync(0xffffffffu, a0, o);
                a1 += __shfl_xor_sync(0xffffffffu, a1, o);
                a2 += __shfl_xor_sync(0xffffffffu, a2, o);
                a3 += __shfl_xor_sync(0xffffffffu, a3, o);
            }
            if (lane == 0) {
                ss[(w * 4 + 0) * SVP + j0 + j] = a0 * scale;
                ss[(w * 4 + 1) * SVP + j0 + j] = a1 * scale;
                ss[(w * 4 + 2) * SVP + j0 + j] = a2 * scale;
                ss[(w * 4 + 3) * SVP + j0 + j] = a3 * scale;
            }
        }
        __syncthreads();
    }

#pragma unroll
    for (int i = 0; i < 4; i++) {
        const int q = w * 4 + i;
        float mx = -1e30f;
        for (int j = lane; j < SV; j += 32) mx = fmaxf(mx, ss[q * SVP + j]);
#pragma unroll
        for (int o = 16; o; o >>= 1)
            mx = fmaxf(mx, __shfl_xor_sync(0xffffffffu, mx, o));
        float sum = 0.f;
        for (int j = lane; j < SV; j += 32) {
            const float e = expf(ss[q * SVP + j] - mx);
            ss[q * SVP + j] = e;
            sum += e;
        }
#pragma unroll
        for (int o = 16; o; o >>= 1)
            sum += __shfl_xor_sync(0xffffffffu, sum, o);
        const float inv = 1.f / sum;
        for (int j = lane; j < SV; j += 32) ss[q * SVP + j] *= inv;
    }
    __syncthreads();

    const int q  = tid >> 3;
    const int dg = tid & 7;
    const int d0 = dg * 36;
    float4 acc[9];
#pragma unroll
    for (int i = 0; i < 9; i++) acc[i] = make_float4(0.f, 0.f, 0.f, 0.f);

    const float* vg = Vm + ((size_t)(b * SV)) * DM + h * DK;
    for (int j0 = 0; j0 < SV; j0 += ATT_KC) {
        const int jn = min(ATT_KC, SV - j0);
        __syncthreads();
        for (int idx = tid; idx < jn * DK; idx += 256) {
            const int r = idx / DK, c = idx - r * DK;
            kv[idx] = vg[(size_t)(j0 + r) * DM + c];
        }
        __syncthreads();
        for (int j = 0; j < jn; j++) {
            const float wgt = ss[q * SVP + j0 + j];
#pragma unroll
            for (int i = 0; i < 9; i++) {
                const float4 vv = *(const float4*)&kv[j * DK + d0 + i * 4];
                acc[i].x += wgt * vv.x;  acc[i].y += wgt * vv.y;
                acc[i].z += wgt * vv.z;  acc[i].w += wgt * vv.w;
            }
        }
    }
    float* og = O + ((size_t)(b * SQ + q0 + q)) * DM + h * DK + d0;
#pragma unroll
    for (int i = 0; i < 9; i++) *(float4*)&og[i * 4] = acc[i];
}

// ---------------------------------------------------------------------------
// Orchestration
// ---------------------------------------------------------------------------
extern "C" void kernel_launch(void* const* d_in, const int* in_sizes, int n_in,
                              void* d_out, int out_size)
{
    const float* vision = (const float*)d_in[0];
    const float* text   = (const float*)d_in[1];
    const float* vp_w   = (const float*)d_in[2];
    const float* vp_b   = (const float*)d_in[3];
    const float* ln1_w  = (const float*)d_in[4];
    const float* ln1_b  = (const float*)d_in[5];
    const float* ln2_w  = (const float*)d_in[6];
    const float* ln2_b  = (const float*)d_in[7];
    const float* wq_w   = (const float*)d_in[8];
    const float* wq_b   = (const float*)d_in[9];
    const float* wk_w   = (const float*)d_in[10];
    const float* wk_b   = (const float*)d_in[11];
    const float* wv_w   = (const float*)d_in[12];
    const float* wv_b   = (const float*)d_in[13];
    const float* wo_w   = (const float*)d_in[14];
    const float* wo_b   = (const float*)d_in[15];
    const float* f1_w   = (const float*)d_in[16];
    const float* f1_b   = (const float*)d_in[17];
    const float* f2_w   = (const float*)d_in[18];
    const float* f2_b   = (const float*)d_in[19];
    float* out = (float*)d_out;

    float *pv, *nt, *q, *k, *v, *ctx, *x, *h;
    cudaGetSymbolAddress((void**)&pv,  g_pv);
    cudaGetSymbolAddress((void**)&nt,  g_nt);
    cudaGetSymbolAddress((void**)&q,   g_q);
    cudaGetSymbolAddress((void**)&k,   g_k);
    cudaGetSymbolAddress((void**)&v,   g_v);
    cudaGetSymbolAddress((void**)&ctx, g_ctx);
    cudaGetSymbolAddress((void**)&x,   g_x);
    cudaGetSymbolAddress((void**)&h,   g_h);

    cudaFuncSetAttribute(tgemm<0>, cudaFuncAttributeMaxDynamicSharedMemorySize, GEMM_SMEM);
    cudaFuncSetAttribute(tgemm<1>, cudaFuncAttributeMaxDynamicSharedMemorySize, GEMM_SMEM);
    cudaFuncSetAttribute(tgemm<2>, cudaFuncAttributeMaxDynamicSharedMemorySize, GEMM_SMEM);
    cudaFuncSetAttribute(attention_kernel,
                         cudaFuncAttributeMaxDynamicSharedMemorySize, ATT_SMEM);

    const dim3 blk(256);
    const int mtV = (ROWS_V + TM - 1) / TM;   // 17
    const int mtT = ROWS_T / TM;              // 128

    // 1. pv = vision @ vp_w + vp_b            [2056,1024]x[1024,2304]
    tgemm<0><<<dim3(DM / TN, mtV), blk, GEMM_SMEM>>>(
        vision, vp_w, vp_b, nullptr, pv, ROWS_V, DM, DV);

    // 2. nt = LN1(text)
    layernorm_kernel<<<ROWS_T, 256>>>(text, ln1_w, ln1_b, nt, DM);

    // 3. q = nt @ wq_w + wq_b                 [16384,2304]x[2304,2304]
    tgemm<0><<<dim3(DM / TN, mtT), blk, GEMM_SMEM>>>(
        nt, wq_w, wq_b, nullptr, q, ROWS_T, DM, DM);

    // 4. k = pv @ wk_w + wk_b
    tgemm<0><<<dim3(DM / TN, mtV), blk, GEMM_SMEM>>>(
        pv, wk_w, wk_b, nullptr, k, ROWS_V, DM, DM);

    // 5. v = pv @ wv_w + wv_b
    tgemm<0><<<dim3(DM / TN, mtV), blk, GEMM_SMEM>>>(
        pv, wv_w, wv_b, nullptr, v, ROWS_V, DM, DM);

    // 6. ctx = softmax(q k^T / sqrt(dk)) v
    attention_kernel<<<dim3(SQ / ATT_TQ, BATCH * NH), 256, ATT_SMEM>>>(
        q, k, v, ctx);

    // 7. x = text + ctx @ wo_w + wo_b
    tgemm<1><<<dim3(DM / TN, mtT), blk, GEMM_SMEM>>>(
        ctx, wo_w, wo_b, text, x, ROWS_T, DM, DM);

    // 8. nt = LN2(x)
    layernorm_kernel<<<ROWS_T, 256>>>(x, ln2_w, ln2_b, nt, DM);

    // 9. h = gelu(nt @ f1_w + f1_b)           [16384,2304]x[2304,9216]
    tgemm<2><<<dim3(DF / TN, mtT), blk, GEMM_SMEM>>>(
        nt, f1_w, f1_b, nullptr, h, ROWS_T, DF, DM);

    // 10. out = x + h @ f2_w + f2_b           [16384,9216]x[9216,2304]
    tgemm<1><<<dim3(DM / TN, mtT), blk, GEMM_SMEM>>>(
        h, f2_w, f2_b, x, out, ROWS_T, DM, DF);
}

// round 5
// speedup vs baseline: 1.0242x; 1.0242x over previous
#include <cuda_runtime.h>
#include <cuda_bf16.h>
#include <math.h>
#include <cstdint>

// ---------------------------------------------------------------------------
// Problem constants
// ---------------------------------------------------------------------------
#define BATCH 8
#define SV    257
#define SQ    2048
#define DV    1024
#define DM    2304
#define NH    8
#define DK    288
#define DF    9216
#define ROWS_T (BATCH*SQ)  // 16384
#define ROWS_V (BATCH*SV)  // 2056

// ---------------------------------------------------------------------------
// Scratch (device globals; no runtime allocation allowed)
// ---------------------------------------------------------------------------
__device__ float g_pv [(size_t)ROWS_V * DM];
__device__ float g_nt [(size_t)ROWS_T * DM];
__device__ float g_q  [(size_t)ROWS_T * DM];
__device__ float g_k  [(size_t)ROWS_V * DM];
__device__ float g_v  [(size_t)ROWS_V * DM];
__device__ float g_ctx[(size_t)ROWS_T * DM];
__device__ float g_x  [(size_t)ROWS_T * DM];
__device__ float g_h  [(size_t)ROWS_T * DF];
// tf32-rounded weight copies + vision copy
#define OFF_VP 0
#define OFF_WQ (OFF_VP + DV*DM)
#define OFF_WK (OFF_WQ + DM*DM)
#define OFF_WV (OFF_WK + DM*DM)
#define OFF_WO (OFF_WV + DM*DM)
#define OFF_F1 (OFF_WO + DM*DM)
#define OFF_F2 (OFF_F1 + (size_t)DM*DF)
#define WR_TOTAL (OFF_F2 + (size_t)DF*DM)
__device__ float g_wr [WR_TOTAL];
__device__ float g_vis[(size_t)ROWS_V * DV];

// ---------------------------------------------------------------------------
// helpers
// ---------------------------------------------------------------------------
__device__ __forceinline__ uint32_t smem_u32(const void* p) {
    uint32_t a;
    asm("{ .reg .u64 t; cvta.to.shared.u64 t, %1; cvt.u32.u64 %0, t; }"
        : "=r"(a) : "l"(p));
    return a;
}
__device__ __forceinline__ void cp16(uint32_t dst, const void* src, uint32_t n) {
    asm volatile("cp.async.cg.shared.global [%0], [%1], 16, %2;"
                 :: "r"(dst), "l"(src), "r"(n) : "memory");
}
__device__ __forceinline__ float f2tf_f(float x) {
    uint32_t r;
    asm("cvt.rna.tf32.f32 %0, %1;" : "=r"(r) : "f"(x));
    return __uint_as_float(r);
}
__device__ __forceinline__ void mma_tf32(float* c, const uint32_t* a,
                                         const uint32_t* b) {
    asm volatile(
        "mma.sync.aligned.m16n8k8.row.col.f32.tf32.tf32.f32 "
        "{%0,%1,%2,%3}, {%4,%5,%6,%7}, {%8,%9}, {%0,%1,%2,%3};"
        : "+f"(c[0]), "+f"(c[1]), "+f"(c[2]), "+f"(c[3])
        : "r"(a[0]), "r"(a[1]), "r"(a[2]), "r"(a[3]), "r"(b[0]), "r"(b[1]));
}
__device__ __forceinline__ float gelu_exact(float x) {
    return 0.5f * x * (1.0f + erff(x * 0.70710678118654752f));
}

// ---------------------------------------------------------------------------
// elementwise tf32 rounding (weights / vision), grid-stride
// ---------------------------------------------------------------------------
__global__ void __launch_bounds__(256)
round_tf32_kernel(const float* __restrict__ in, float* __restrict__ out,
                  size_t n)
{
    for (size_t i = (size_t)blockIdx.x * 256 + threadIdx.x; i < n;
         i += (size_t)gridDim.x * 256)
        out[i] = f2tf_f(in[i]);
}

// ---------------------------------------------------------------------------
// tf32 HMMA GEMM: C[M,N] = A[M,K] @ B[K,N] + bias (+ epilogue)
//   EPI 0: +bias   EPI 1: +bias+res   EPI 2: gelu(+bias)
//   RND 1: round written output to tf32 (it feeds a later GEMM as A operand)
// A and B must ALREADY be tf32-rounded (raw bits fed to HMMA).
// CTA tile 128x256, KC=32, 3-stage cp.async, 512 thr, 16 warps x (64x32).
// Requires: K % 32 == 0, N % 256 == 0, K/32 >= 3. M tail handled.
// ---------------------------------------------------------------------------
#define TM 128
#define TN 256
#define KC 32
#define NSTG 3
#define A_BYTES 16384                 // 128 x 32 x 4
#define STG_BYTES 49152               // A 16KB + B 32KB
#define GEMM_SMEM (NSTG * STG_BYTES)  // 147456

// A smem: row-major [128][32] floats, col swizz: c = (k + 4*(row&7)) & 31
// B smem: row-major [32][256] floats, col swizz: c = (n&~31) | ((n + 8*(k&3)) & 31)

__device__ __forceinline__ void load_stage(
    const float* __restrict__ A, const float* __restrict__ Bw,
    int M, int N, int K, uint32_t stg, int bm, int n0, int kc, int tid)
{
#pragma unroll
    for (int i = 0; i < 2; i++) {            // A: 1024 cp16 / 512 thr
        const int ai = tid + i * 512;
        const int row = ai >> 3, c4 = ai & 7;
        const uint32_t col = (uint32_t)((c4 * 4 + 4 * (row & 7)) & 31);
        const uint32_t dst = stg + row * 128 + col * 4;
        const int gr = bm + row;
        const int ok = gr < M;
        const float* src = A + (size_t)(ok ? gr : 0) * K + kc + c4 * 4;
        cp16(dst, src, ok ? 16u : 0u);
    }
#pragma unroll
    for (int i = 0; i < 4; i++) {            // B: 2048 cp16 / 512 thr
        const int bi = tid + i * 512;
        const int k = bi >> 6, c4 = bi & 63;
        const int n = c4 * 4;
        const uint32_t col = (uint32_t)((n & ~31) | ((n + 8 * (k & 3)) & 31));
        const uint32_t dst = stg + A_BYTES + k * 1024 + col * 4;
        const float* src = Bw + (size_t)(kc + k) * N + n0 + n;
        cp16(dst, src, 16u);
    }
}

template <int EPI, int RND>
__global__ void __launch_bounds__(512, 1)
tgemm(const float* __restrict__ A, const float* __restrict__ Bw,
      const float* __restrict__ bias, const float* __restrict__ res,
      float* __restrict__ C, int M, int N, int K)
{
    extern __shared__ char smem[];
    const uint32_t sb = smem_u32(smem);
    const int tid  = threadIdx.x;
    const int lane = tid & 31;
    const int wid  = tid >> 5;
    const int wm   = (wid >> 3) * 64;     // warp row offset (0, 64)
    const int wn   = (wid & 7) * 32;      // warp col offset (0..224)
    const int bm   = blockIdx.y * TM;
    const int n0   = blockIdx.x * TN;
    const int nch  = K / KC;

    float c[4][4][4];
#pragma unroll
    for (int mt = 0; mt < 4; mt++)
#pragma unroll
        for (int nt = 0; nt < 4; nt++)
#pragma unroll
            for (int r = 0; r < 4; r++) c[mt][nt][r] = 0.f;

    // prologue: stages 0,1 (nch >= 3 at all call sites)
    load_stage(A, Bw, M, N, K, sb, bm, n0, 0, tid);
    asm volatile("cp.async.commit_group;" ::: "memory");
    load_stage(A, Bw, M, N, K, sb + STG_BYTES, bm, n0, KC, tid);
    asm volatile("cp.async.commit_group;" ::: "memory");

    const int l4 = lane >> 2;      // 0..7
    const int lk = lane & 3;       // 0..3

    for (int chunk = 0; chunk < nch; ++chunk) {
        asm volatile("cp.async.wait_group 1;" ::: "memory");
        __syncthreads();

        // issue next-chunk loads first (overlaps gmem latency with math)
        const int nx = chunk + 2;
        if (nx < nch)
            load_stage(A, Bw, M, N, K, sb + (nx % NSTG) * STG_BYTES,
                       bm, n0, nx * KC, tid);
        asm volatile("cp.async.commit_group;" ::: "memory");

        const char* stage = smem + (chunk % NSTG) * STG_BYTES;
        const float* As = (const float*)stage;
        const float* Bs = (const float*)(stage + A_BYTES);

#pragma unroll
        for (int ks = 0; ks < 4; ks++) {
            const int k0 = ks * 8 + lk;
            const int k1 = k0 + 4;
            uint32_t a[16], b[8];
#pragma unroll
            for (int mt = 0; mt < 4; mt++) {
                const int r0 = wm + mt * 16 + l4;
                const int r1 = r0 + 8;
                a[mt*4+0] = __float_as_uint(As[r0 * 32 + ((k0 + 4 * (r0 & 7)) & 31)]);
                a[mt*4+1] = __float_as_uint(As[r1 * 32 + ((k0 + 4 * (r1 & 7)) & 31)]);
                a[mt*4+2] = __float_as_uint(As[r0 * 32 + ((k1 + 4 * (r0 & 7)) & 31)]);
                a[mt*4+3] = __float_as_uint(As[r1 * 32 + ((k1 + 4 * (r1 & 7)) & 31)]);
            }
#pragma unroll
            for (int nt = 0; nt < 4; nt++) {
                const int n = wn + nt * 8 + l4;
                const int sw = n & ~31;
                b[nt*2+0] = __float_as_uint(Bs[k0 * 256 + (sw | ((n + 8 * (k0 & 3)) & 31))]);
                b[nt*2+1] = __float_as_uint(Bs[k1 * 256 + (sw | ((n + 8 * (k1 & 3)) & 31))]);
            }
#pragma unroll
            for (int mt = 0; mt < 4; mt++)
#pragma unroll
                for (int nt = 0; nt < 4; nt++)
                    mma_tf32(c[mt][nt], &a[mt * 4], &b[nt * 2]);
        }
    }

    // -------- epilogue --------
#pragma unroll
    for (int mt = 0; mt < 4; mt++) {
        const int rb = bm + wm + mt * 16 + l4;
#pragma unroll
        for (int hh = 0; hh < 2; hh++) {
            const int row = rb + hh * 8;
            if (row < M) {
#pragma unroll
                for (int nt = 0; nt < 4; nt++) {
                    const int col = n0 + wn + nt * 8 + lk * 2;
                    float v0 = c[mt][nt][hh * 2 + 0] + bias[col];
                    float v1 = c[mt][nt][hh * 2 + 1] + bias[col + 1];
                    if (EPI == 1) {
                        const float2 r2 = *(const float2*)&res[(size_t)row * N + col];
                        v0 += r2.x; v1 += r2.y;
                    } else if (EPI == 2) {
                        v0 = gelu_exact(v0); v1 = gelu_exact(v1);
                    }
                    if (RND) { v0 = f2tf_f(v0); v1 = f2tf_f(v1); }
                    *(float2*)&C[(size_t)row * N + col] = make_float2(v0, v1);
                }
            }
        }
    }
}

// ---------------------------------------------------------------------------
// LayerNorm over last dim (C = DM), one block per row.
// Output is tf32-rounded (it always feeds a GEMM A operand).
// ---------------------------------------------------------------------------
__global__ void __launch_bounds__(256)
layernorm_kernel(const float* __restrict__ x, const float* __restrict__ w,
                 const float* __restrict__ bta, float* __restrict__ y, int C)
{
    const size_t base = (size_t)blockIdx.x * C;
    float s = 0.f, s2 = 0.f;
    for (int c = threadIdx.x; c < C; c += 256) {
        const float v = x[base + c];
        s += v; s2 += v * v;
    }
#pragma unroll
    for (int o = 16; o; o >>= 1) {
        s  += __shfl_xor_sync(0xffffffffu, s,  o);
        s2 += __shfl_xor_sync(0xffffffffu, s2, o);
    }
    __shared__ float sh[16];
    __shared__ float mv[2];
    const int wid = threadIdx.x >> 5, lane = threadIdx.x & 31;
    if (lane == 0) { sh[wid] = s; sh[8 + wid] = s2; }
    __syncthreads();
    if (threadIdx.x == 0) {
        float ts = 0.f, ts2 = 0.f;
#pragma unroll
        for (int i = 0; i < 8; i++) { ts += sh[i]; ts2 += sh[8 + i]; }
        const float mean = ts / (float)C;
        const float var  = ts2 / (float)C - mean * mean;
        mv[0] = mean;
        mv[1] = rsqrtf(var + 1e-5f);
    }
    __syncthreads();
    const float mean = mv[0], rstd = mv[1];
    for (int c = threadIdx.x; c < C; c += 256)
        y[base + c] = f2tf_f((x[base + c] - mean) * rstd * w[c] + bta[c]);
}

// ---------------------------------------------------------------------------
// Cross attention (fp32). Output ctx is tf32-rounded (feeds GEMM 7 as A).
// ---------------------------------------------------------------------------
#define ATT_TQ 32
#define ATT_KC 32
#define SVP    260
#define ATT_SMEM ((ATT_TQ*DK + ATT_TQ*SVP + ATT_KC*DK) * (int)sizeof(float))

__global__ void __launch_bounds__(256)
attention_kernel(const float* __restrict__ Q, const float* __restrict__ Km,
                 const float* __restrict__ Vm, float* __restrict__ O)
{
    extern __shared__ float sm[];
    float* qs = sm;
    float* ss = qs + ATT_TQ * DK;
    float* kv = ss + ATT_TQ * SVP;

    const int q0   = blockIdx.x * ATT_TQ;
    const int b    = blockIdx.y / NH;
    const int h    = blockIdx.y % NH;
    const int tid  = threadIdx.x;
    const int lane = tid & 31;
    const int w    = tid >> 5;
    const float scale = 0.05892556509887896f;   // 1/sqrt(288)

    const float* qg = Q + ((size_t)(b * SQ + q0)) * DM + h * DK;
    for (int idx = tid; idx < ATT_TQ * DK; idx += 256) {
        const int r = idx / DK, c = idx - r * DK;
        qs[idx] = qg[(size_t)r * DM + c];
    }
    __syncthreads();

    float qr[4][9];
#pragma unroll
    for (int i = 0; i < 4; i++)
#pragma unroll
        for (int t = 0; t < 9; t++)
            qr[i][t] = qs[(w * 4 + i) * DK + lane + t * 32];

    const float* kg = Km + ((size_t)(b * SV)) * DM + h * DK;
    for (int j0 = 0; j0 < SV; j0 += ATT_KC) {
        const int jn = min(ATT_KC, SV - j0);
        for (int idx = tid; idx < jn * DK; idx += 256) {
            const int r = idx / DK, c = idx - r * DK;
            kv[idx] = kg[(size_t)(j0 + r) * DM + c];
        }
        __syncthreads();
        for (int j = 0; j < jn; j++) {
            float a0 = 0.f, a1 = 0.f, a2 = 0.f, a3 = 0.f;
#pragma unroll
            for (int t = 0; t < 9; t++) {
                const float kvv = kv[j * DK + lane + t * 32];
                a0 += qr[0][t] * kvv;  a1 += qr[1][t] * kvv;
                a2 += qr[2][t] * kvv;  a3 += qr[3][t] * kvv;
            }
#pragma unroll
            for (int o = 16; o; o >>= 1) {
                a0 += __shfl_xor_sync(0xffffffffu, a0, o);
                a1 += __shfl_xor_sync(0xffffffffu, a1, o);
                a2 += __shfl_xor_sync(0xffffffffu, a2, o);
                a3 += __shfl_xor_sync(0xffffffffu, a3, o);
            }
            if (lane == 0) {
                ss[(w * 4 + 0) * SVP + j0 + j] = a0 * scale;
                ss[(w * 4 + 1) * SVP + j0 + j] = a1 * scale;
                ss[(w * 4 + 2) * SVP + j0 + j] = a2 * scale;
                ss[(w * 4 + 3) * SVP + j0 + j] = a3 * scale;
            }
        }
        __syncthreads();
    }

#pragma unroll
    for (int i = 0; i < 4; i++) {
        const int q = w * 4 + i;
        float mx = -1e30f;
        for (int j = lane; j < SV; j += 32) mx = fmaxf(mx, ss[q * SVP + j]);
#pragma unroll
        for (int o = 16; o; o >>= 1)
            mx = fmaxf(mx, __shfl_xor_sync(0xffffffffu, mx, o));
        float sum = 0.f;
        for (int j = lane; j < SV; j += 32) {
            const float e = expf(ss[q * SVP + j] - mx);
            ss[q * SVP + j] = e;
            sum += e;
        }
#pragma unroll
        for (int o = 16; o; o >>= 1)
            sum += __shfl_xor_sync(0xffffffffu, sum, o);
        const float inv = 1.f / sum;
        for (int j = lane; j < SV; j += 32) ss[q * SVP + j] *= inv;
    }
    __syncthreads();

    const int q  = tid >> 3;
    const int dg = tid & 7;
    const int d0 = dg * 36;
    float4 acc[9];
#pragma unroll
    for (int i = 0; i < 9; i++) acc[i] = make_float4(0.f, 0.f, 0.f, 0.f);

    const float* vg = Vm + ((size_t)(b * SV)) * DM + h * DK;
    for (int j0 = 0; j0 < SV; j0 += ATT_KC) {
        const int jn = min(ATT_KC, SV - j0);
        __syncthreads();
        for (int idx = tid; idx < jn * DK; idx += 256) {
            const int r = idx / DK, c = idx - r * DK;
            kv[idx] = vg[(size_t)(j0 + r) * DM + c];
        }
        __syncthreads();
        for (int j = 0; j < jn; j++) {
            const float wgt = ss[q * SVP + j0 + j];
#pragma unroll
            for (int i = 0; i < 9; i++) {
                const float4 vv = *(const float4*)&kv[j * DK + d0 + i * 4];
                acc[i].x += wgt * vv.x;  acc[i].y += wgt * vv.y;
                acc[i].z += wgt * vv.z;  acc[i].w += wgt * vv.w;
            }
        }
    }
    float* og = O + ((size_t)(b * SQ + q0 + q)) * DM + h * DK + d0;
#pragma unroll
    for (int i = 0; i < 9; i++) {
        float4 r = acc[i];
        r.x = f2tf_f(r.x); r.y = f2tf_f(r.y);
        r.z = f2tf_f(r.z); r.w = f2tf_f(r.w);
        *(float4*)&og[i * 4] = r;
    }
}

// ---------------------------------------------------------------------------
// Orchestration
// ---------------------------------------------------------------------------
extern "C" void kernel_launch(void* const* d_in, const int* in_sizes, int n_in,
                              void* d_out, int out_size)
{
    const float* vision = (const float*)d_in[0];
    const float* text   = (const float*)d_in[1];
    const float* vp_w   = (const float*)d_in[2];
    const float* vp_b   = (const float*)d_in[3];
    const float* ln1_w  = (const float*)d_in[4];
    const float* ln1_b  = (const float*)d_in[5];
    const float* ln2_w  = (const float*)d_in[6];
    const float* ln2_b  = (const float*)d_in[7];
    const float* wq_w   = (const float*)d_in[8];
    const float* wq_b   = (const float*)d_in[9];
    const float* wk_w   = (const float*)d_in[10];
    const float* wk_b   = (const float*)d_in[11];
    const float* wv_w   = (const float*)d_in[12];
    const float* wv_b   = (const float*)d_in[13];
    const float* wo_w   = (const float*)d_in[14];
    const float* wo_b   = (const float*)d_in[15];
    const float* f1_w   = (const float*)d_in[16];
    const float* f1_b   = (const float*)d_in[17];
    const float* f2_w   = (const float*)d_in[18];
    const float* f2_b   = (const float*)d_in[19];
    float* out = (float*)d_out;

    float *pv, *nt, *q, *k, *v, *ctx, *x, *h, *wr, *vis;
    cudaGetSymbolAddress((void**)&pv,  g_pv);
    cudaGetSymbolAddress((void**)&nt,  g_nt);
    cudaGetSymbolAddress((void**)&q,   g_q);
    cudaGetSymbolAddress((void**)&k,   g_k);
    cudaGetSymbolAddress((void**)&v,   g_v);
    cudaGetSymbolAddress((void**)&ctx, g_ctx);
    cudaGetSymbolAddress((void**)&x,   g_x);
    cudaGetSymbolAddress((void**)&h,   g_h);
    cudaGetSymbolAddress((void**)&wr,  g_wr);
    cudaGetSymbolAddress((void**)&vis, g_vis);

    cudaFuncSetAttribute(tgemm<0,0>, cudaFuncAttributeMaxDynamicSharedMemorySize, GEMM_SMEM);
    cudaFuncSetAttribute(tgemm<0,1>, cudaFuncAttributeMaxDynamicSharedMemorySize, GEMM_SMEM);
    cudaFuncSetAttribute(tgemm<1,0>, cudaFuncAttributeMaxDynamicSharedMemorySize, GEMM_SMEM);
    cudaFuncSetAttribute(tgemm<2,1>, cudaFuncAttributeMaxDynamicSharedMemorySize, GEMM_SMEM);
    cudaFuncSetAttribute(attention_kernel,
                         cudaFuncAttributeMaxDynamicSharedMemorySize, ATT_SMEM);

    // ---- 0. round weights + vision input to tf32 ----
    round_tf32_kernel<<<2048, 256>>>(vision, vis, (size_t)ROWS_V * DV);
    round_tf32_kernel<<<2048, 256>>>(vp_w, wr + OFF_VP, (size_t)DV * DM);
    round_tf32_kernel<<<2048, 256>>>(wq_w, wr + OFF_WQ, (size_t)DM * DM);
    round_tf32_kernel<<<2048, 256>>>(wk_w, wr + OFF_WK, (size_t)DM * DM);
    round_tf32_kernel<<<2048, 256>>>(wv_w, wr + OFF_WV, (size_t)DM * DM);
    round_tf32_kernel<<<2048, 256>>>(wo_w, wr + OFF_WO, (size_t)DM * DM);
    round_tf32_kernel<<<2048, 256>>>(f1_w, wr + OFF_F1, (size_t)DM * DF);
    round_tf32_kernel<<<2048, 256>>>(f2_w, wr + OFF_F2, (size_t)DF * DM);

    const dim3 blk(512);
    const int mtV = (ROWS_V + TM - 1) / TM;   // 17
    const int mtT = ROWS_T / TM;              // 128

    // 1. pv = vision @ vp_w + vp_b  (pv rounded: feeds GEMM 4/5 as A)
    tgemm<0,1><<<dim3(DM / TN, mtV), blk, GEMM_SMEM>>>(
        vis, wr + OFF_VP, vp_b, nullptr, pv, ROWS_V, DM, DV);

    // 2. nt = LN1(text)  (rounded in-kernel)
    layernorm_kernel<<<ROWS_T, 256>>>(text, ln1_w, ln1_b, nt, DM);

    // 3. q = nt @ wq_w + wq_b
    tgemm<0,0><<<dim3(DM / TN, mtT), blk, GEMM_SMEM>>>(
        nt, wr + OFF_WQ, wq_b, nullptr, q, ROWS_T, DM, DM);

    // 4. k = pv @ wk_w + wk_b
    tgemm<0,0><<<dim3(DM / TN, mtV), blk, GEMM_SMEM>>>(
        pv, wr + OFF_WK, wk_b, nullptr, k, ROWS_V, DM, DM);

    // 5. v = pv @ wv_w + wv_b
    tgemm<0,0><<<dim3(DM / TN, mtV), blk, GEMM_SMEM>>>(
        pv, wr + OFF_WV, wv_b, nullptr, v, ROWS_V, DM, DM);

    // 6. ctx = softmax(q k^T / sqrt(dk)) v   (ctx rounded in-kernel)
    attention_kernel<<<dim3(SQ / ATT_TQ, BATCH * NH), 256, ATT_SMEM>>>(
        q, k, v, ctx);

    // 7. x = text + ctx @ wo_w + wo_b
    tgemm<1,0><<<dim3(DM / TN, mtT), blk, GEMM_SMEM>>>(
        ctx, wr + OFF_WO, wo_b, text, x, ROWS_T, DM, DM);

    // 8. nt = LN2(x)  (rounded in-kernel)
    layernorm_kernel<<<ROWS_T, 256>>>(x, ln2_w, ln2_b, nt, DM);

    // 9. h = gelu(nt @ f1_w + f1_b)  (h rounded: feeds GEMM 10 as A)
    tgemm<2,1><<<dim3(DF / TN, mtT), blk, GEMM_SMEM>>>(
        nt, wr + OFF_F1, f1_b, nullptr, h, ROWS_T, DF, DM);

    // 10. out = x + h @ f2_w + f2_b
    tgemm<1,0><<<dim3(DM / TN, mtT), blk, GEMM_SMEM>>>(
        h, wr + OFF_F2, f2_b, x, out, ROWS_T, DM, DF);
}

// round 6
// speedup vs baseline: 1.4809x; 1.4459x over previous
#include <cuda_runtime.h>
#include <cuda_fp16.h>
#include <math.h>
#include <cstdint>

// ---------------------------------------------------------------------------
// Problem constants
// ---------------------------------------------------------------------------
#define BATCH 8
#define SV    257
#define SQ    2048
#define DV    1024
#define DM    2304
#define NH    8
#define DK    288
#define DF    9216
#define ROWS_T (BATCH*SQ)  // 16384
#define ROWS_V (BATCH*SV)  // 2056

// ---------------------------------------------------------------------------
// Scratch (device globals; no runtime allocation allowed)
// ---------------------------------------------------------------------------
__device__ float  g_q  [(size_t)ROWS_T * DM];
__device__ float  g_k  [(size_t)ROWS_V * DM];
__device__ float  g_v  [(size_t)ROWS_V * DM];
__device__ float  g_x  [(size_t)ROWS_T * DM];
__device__ __half g_pv [(size_t)ROWS_V * DM];
__device__ __half g_nt [(size_t)ROWS_T * DM];
__device__ __half g_ctx[(size_t)ROWS_T * DM];
__device__ __half g_h  [(size_t)ROWS_T * DF];
__device__ __half g_vis[(size_t)ROWS_V * DV];
// fp16 weight copies
#define OFF_VP 0
#define OFF_WQ (OFF_VP + (size_t)DV*DM)
#define OFF_WK (OFF_WQ + (size_t)DM*DM)
#define OFF_WV (OFF_WK + (size_t)DM*DM)
#define OFF_WO (OFF_WV + (size_t)DM*DM)
#define OFF_F1 (OFF_WO + (size_t)DM*DM)
#define OFF_F2 (OFF_F1 + (size_t)DM*DF)
#define W16_TOTAL (OFF_F2 + (size_t)DF*DM)
__device__ __half g_w16[W16_TOTAL];

// ---------------------------------------------------------------------------
// helpers
// ---------------------------------------------------------------------------
__device__ __forceinline__ uint32_t smem_u32(const void* p) {
    uint32_t a;
    asm("{ .reg .u64 t; cvta.to.shared.u64 t, %1; cvt.u32.u64 %0, t; }"
        : "=r"(a) : "l"(p));
    return a;
}
__device__ __forceinline__ void cp16(uint32_t dst, const void* src, uint32_t n) {
    asm volatile("cp.async.cg.shared.global [%0], [%1], 16, %2;"
                 :: "r"(dst), "l"(src), "r"(n) : "memory");
}
__device__ __forceinline__ void ldsm_x4(uint32_t* r, uint32_t addr) {
    asm volatile("ldmatrix.sync.aligned.m8n8.x4.shared.b16 {%0,%1,%2,%3}, [%4];"
        : "=r"(r[0]), "=r"(r[1]), "=r"(r[2]), "=r"(r[3]) : "r"(addr));
}
__device__ __forceinline__ void ldsm_x4_t(uint32_t* r, uint32_t addr) {
    asm volatile("ldmatrix.sync.aligned.m8n8.x4.trans.shared.b16 {%0,%1,%2,%3}, [%4];"
        : "=r"(r[0]), "=r"(r[1]), "=r"(r[2]), "=r"(r[3]) : "r"(addr));
}
__device__ __forceinline__ void mma_f16(float* c, const uint32_t* a,
                                        const uint32_t* b) {
    asm volatile(
        "mma.sync.aligned.m16n8k16.row.col.f32.f16.f16.f32 "
        "{%0,%1,%2,%3}, {%4,%5,%6,%7}, {%8,%9}, {%0,%1,%2,%3};"
        : "+f"(c[0]), "+f"(c[1]), "+f"(c[2]), "+f"(c[3])
        : "r"(a[0]), "r"(a[1]), "r"(a[2]), "r"(a[3]), "r"(b[0]), "r"(b[1]));
}
__device__ __forceinline__ float gelu_exact(float x) {
    return 0.5f * x * (1.0f + erff(x * 0.70710678118654752f));
}

// ---------------------------------------------------------------------------
// elementwise fp32 -> fp16 conversion, grid-stride
// ---------------------------------------------------------------------------
__global__ void __launch_bounds__(256)
cvt16_kernel(const float* __restrict__ in, __half* __restrict__ out, size_t n)
{
    for (size_t i = (size_t)blockIdx.x * 256 + threadIdx.x; i < n;
         i += (size_t)gridDim.x * 256)
        out[i] = __float2half_rn(in[i]);
}

// ---------------------------------------------------------------------------
// fp16 HMMA GEMM: C[M,N] = A[M,K] @ B[K,N] + bias (+ epilogue)
//   A, B are fp16; bias/res fp32; accumulation fp32.
//   EPI 0: +bias   EPI 1: +bias+res   EPI 2: gelu(+bias)
//   OUT16: write __half output, else float.
// CTA tile 128x256, KC=32, 4-stage cp.async, 512 thr, 16 warps x (64x32).
// Requires: K % 32 == 0, N % 256 == 0, K/32 >= 3. M tail handled.
// ---------------------------------------------------------------------------
#define TM 128
#define TN 256
#define KC 32
#define NSTG 4
#define A_ROWB 80                      // 64B data + 16B pad (bank-spread)
#define A_BYTES (128 * A_ROWB)         // 10240
#define B_BYTES (KC * 512)             // 16384 (256 fp16 per k-row)
#define STG_BYTES (A_BYTES + B_BYTES)  // 26624
#define GEMM_SMEM (NSTG * STG_BYTES)   // 106496

// A smem: row r at r*80, 4 chunks of 16B (8 fp16), no intra-row swizzle
//         (the 80B row stride spreads 8 consecutive rows over all banks).
// B smem: k-row at k*512, chunk c (16B = 8 fp16) stored at (c ^ (k&7))*16.

__device__ __forceinline__ void load_stage(
    const __half* __restrict__ A, const __half* __restrict__ Bw,
    int M, int N, int K, uint32_t stg, int bm, int n0, int kc, int tid)
{
    {   // A: 512 cp16
        const int row = tid >> 2, c = tid & 3;
        const int gr = bm + row;
        const int ok = gr < M;
        const uint32_t dst = stg + row * A_ROWB + c * 16;
        const __half* src = A + (size_t)(ok ? gr : 0) * K + kc + c * 8;
        cp16(dst, src, ok ? 16u : 0u);
    }
#pragma unroll
    for (int j = 0; j < 2; j++) {   // B: 1024 cp16
        const int bi = tid + j * 512;
        const int k = bi >> 5, c = bi & 31;
        const uint32_t dst = stg + A_BYTES + k * 512 + ((c ^ (k & 7)) << 4);
        const __half* src = Bw + (size_t)(kc + k) * N + n0 + c * 8;
        cp16(dst, src, 16u);
    }
}

template <int EPI, int OUT16>
__global__ void __launch_bounds__(512, 1)
hgemm(const __half* __restrict__ A, const __half* __restrict__ Bw,
      const float* __restrict__ bias, const float* __restrict__ res,
      void* __restrict__ Cv, int M, int N, int K)
{
    extern __shared__ char smem[];
    const uint32_t sb = smem_u32(smem);
    const int tid  = threadIdx.x;
    const int lane = tid & 31;
    const int wid  = tid >> 5;
    const int wm   = (wid >> 3) * 64;     // warp row offset (0, 64)
    const int wn   = (wid & 7) * 32;      // warp col offset (0..224)
    const int bm   = blockIdx.y * TM;
    const int n0   = blockIdx.x * TN;
    const int nch  = K / KC;

    float c[4][4][4];
#pragma unroll
    for (int mt = 0; mt < 4; mt++)
#pragma unroll
        for (int nt = 0; nt < 4; nt++)
#pragma unroll
            for (int r = 0; r < 4; r++) c[mt][nt][r] = 0.f;

    // prologue: stages 0,1,2
#pragma unroll
    for (int p = 0; p < 3; p++) {
        load_stage(A, Bw, M, N, K, sb + p * STG_BYTES, bm, n0, p * KC, tid);
        asm volatile("cp.async.commit_group;" ::: "memory");
    }

    // per-lane ldmatrix address components
    const int la_row = wm + (lane & 15);          // + mt*16
    const int la_chk = lane >> 4;                  // 0/1 -> +16B column
    const int lb_k   = lane & 15;                  // + kk*16
    const int lb_chk = (wn >> 3) + (lane >> 4);    // chunk base + 0/1 (+2 for pair 1)

    for (int chunk = 0; chunk < nch; ++chunk) {
        asm volatile("cp.async.wait_group 2;" ::: "memory");
        __syncthreads();

        const int nx = chunk + 3;
        if (nx < nch)
            load_stage(A, Bw, M, N, K, sb + (nx & (NSTG - 1)) * STG_BYTES,
                       bm, n0, nx * KC, tid);
        asm volatile("cp.async.commit_group;" ::: "memory");

        const uint32_t stgA = sb + (chunk & (NSTG - 1)) * STG_BYTES;
        const uint32_t stgB = stgA + A_BYTES;

#pragma unroll
        for (int kk = 0; kk < 2; kk++) {
            uint32_t a[4][4], bfr[2][4];
#pragma unroll
            for (int mt = 0; mt < 4; mt++)
                ldsm_x4(a[mt], stgA + (la_row + mt * 16) * A_ROWB +
                               (kk * 2 + la_chk) * 16);
            {
                const int k = kk * 16 + lb_k;
                const uint32_t krow = stgB + k * 512;
                const int swk = k & 7;
                ldsm_x4_t(bfr[0], krow + (((lb_chk    ) ^ swk) << 4));
                ldsm_x4_t(bfr[1], krow + (((lb_chk + 2) ^ swk) << 4));
            }
#pragma unroll
            for (int mt = 0; mt < 4; mt++)
#pragma unroll
                for (int nt = 0; nt < 4; nt++)
                    mma_f16(c[mt][nt], a[mt], &bfr[nt >> 1][(nt & 1) * 2]);
        }
    }

    // -------- epilogue --------
    const int l4 = lane >> 2;
    const int lk = lane & 3;
#pragma unroll
    for (int mt = 0; mt < 4; mt++) {
        const int rb = bm + wm + mt * 16 + l4;
#pragma unroll
        for (int hh = 0; hh < 2; hh++) {
            const int row = rb + hh * 8;
            if (row < M) {
#pragma unroll
                for (int nt = 0; nt < 4; nt++) {
                    const int col = n0 + wn + nt * 8 + lk * 2;
                    float v0 = c[mt][nt][hh * 2 + 0] + bias[col];
                    float v1 = c[mt][nt][hh * 2 + 1] + bias[col + 1];
                    if (EPI == 1) {
                        const float2 r2 = *(const float2*)&res[(size_t)row * N + col];
                        v0 += r2.x; v1 += r2.y;
                    } else if (EPI == 2) {
                        v0 = gelu_exact(v0); v1 = gelu_exact(v1);
                    }
                    if (OUT16) {
                        __half2* C = (__half2*)Cv;
                        C[((size_t)row * N + col) >> 1] =
                            __floats2half2_rn(v0, v1);
                    } else {
                        float* C = (float*)Cv;
                        *(float2*)&C[(size_t)row * N + col] = make_float2(v0, v1);
                    }
                }
            }
        }
    }
}

// ---------------------------------------------------------------------------
// LayerNorm over last dim (C = DM), one block per row; fp16 output
// (it always feeds a GEMM A operand).
// ---------------------------------------------------------------------------
__global__ void __launch_bounds__(256)
layernorm_kernel(const float* __restrict__ x, const float* __restrict__ w,
                 const float* __restrict__ bta, __half* __restrict__ y, int C)
{
    const size_t base = (size_t)blockIdx.x * C;
    float s = 0.f, s2 = 0.f;
    for (int c = threadIdx.x; c < C; c += 256) {
        const float v = x[base + c];
        s += v; s2 += v * v;
    }
#pragma unroll
    for (int o = 16; o; o >>= 1) {
        s  += __shfl_xor_sync(0xffffffffu, s,  o);
        s2 += __shfl_xor_sync(0xffffffffu, s2, o);
    }
    __shared__ float sh[16];
    __shared__ float mv[2];
    const int wid = threadIdx.x >> 5, lane = threadIdx.x & 31;
    if (lane == 0) { sh[wid] = s; sh[8 + wid] = s2; }
    __syncthreads();
    if (threadIdx.x == 0) {
        float ts = 0.f, ts2 = 0.f;
#pragma unroll
        for (int i = 0; i < 8; i++) { ts += sh[i]; ts2 += sh[8 + i]; }
        const float mean = ts / (float)C;
        const float var  = ts2 / (float)C - mean * mean;
        mv[0] = mean;
        mv[1] = rsqrtf(var + 1e-5f);
    }
    __syncthreads();
    const float mean = mv[0], rstd = mv[1];
    for (int c = threadIdx.x; c < C; c += 256)
        y[base + c] = __float2half_rn((x[base + c] - mean) * rstd * w[c] + bta[c]);
}

// ---------------------------------------------------------------------------
// Cross attention (fp32 math, fp16 ctx output — feeds GEMM 7 as A operand)
// ---------------------------------------------------------------------------
#define ATT_TQ 32
#define ATT_KC 32
#define SVP    260
#define ATT_SMEM ((ATT_TQ*DK + ATT_TQ*SVP + ATT_KC*DK) * (int)sizeof(float))

__global__ void __launch_bounds__(256)
attention_kernel(const float* __restrict__ Q, const float* __restrict__ Km,
                 const float* __restrict__ Vm, __half* __restrict__ O)
{
    extern __shared__ float sm[];
    float* qs = sm;
    float* ss = qs + ATT_TQ * DK;
    float* kv = ss + ATT_TQ * SVP;

    const int q0   = blockIdx.x * ATT_TQ;
    const int b    = blockIdx.y / NH;
    const int h    = blockIdx.y % NH;
    const int tid  = threadIdx.x;
    const int lane = tid & 31;
    const int w    = tid >> 5;
    const float scale = 0.05892556509887896f;   // 1/sqrt(288)

    const float* qg = Q + ((size_t)(b * SQ + q0)) * DM + h * DK;
    for (int idx = tid; idx < ATT_TQ * DK; idx += 256) {
        const int r = idx / DK, c = idx - r * DK;
        qs[idx] = qg[(size_t)r * DM + c];
    }
    __syncthreads();

    float qr[4][9];
#pragma unroll
    for (int i = 0; i < 4; i++)
#pragma unroll
        for (int t = 0; t < 9; t++)
            qr[i][t] = qs[(w * 4 + i) * DK + lane + t * 32];

    const float* kg = Km + ((size_t)(b * SV)) * DM + h * DK;
    for (int j0 = 0; j0 < SV; j0 += ATT_KC) {
        const int jn = min(ATT_KC, SV - j0);
        for (int idx = tid; idx < jn * DK; idx += 256) {
            const int r = idx / DK, c = idx - r * DK;
            kv[idx] = kg[(size_t)(j0 + r) * DM + c];
        }
        __syncthreads();
        for (int j = 0; j < jn; j++) {
            float a0 = 0.f, a1 = 0.f, a2 = 0.f, a3 = 0.f;
#pragma unroll
            for (int t = 0; t < 9; t++) {
                const float kvv = kv[j * DK + lane + t * 32];
                a0 += qr[0][t] * kvv;  a1 += qr[1][t] * kvv;
                a2 += qr[2][t] * kvv;  a3 += qr[3][t] * kvv;
            }
#pragma unroll
            for (int o = 16; o; o >>= 1) {
                a0 += __shfl_xor_sync(0xffffffffu, a0, o);
                a1 += __shfl_xor_sync(0xffffffffu, a1, o);
                a2 += __shfl_xor_sync(0xffffffffu, a2, o);
                a3 += __shfl_xor_sync(0xffffffffu, a3, o);
            }
            if (lane == 0) {
                ss[(w * 4 + 0) * SVP + j0 + j] = a0 * scale;
                ss[(w * 4 + 1) * SVP + j0 + j] = a1 * scale;
                ss[(w * 4 + 2) * SVP + j0 + j] = a2 * scale;
                ss[(w * 4 + 3) * SVP + j0 + j] = a3 * scale;
            }
        }
        __syncthreads();
    }

#pragma unroll
    for (int i = 0; i < 4; i++) {
        const int q = w * 4 + i;
        float mx = -1e30f;
        for (int j = lane; j < SV; j += 32) mx = fmaxf(mx, ss[q * SVP + j]);
#pragma unroll
        for (int o = 16; o; o >>= 1)
            mx = fmaxf(mx, __shfl_xor_sync(0xffffffffu, mx, o));
        float sum = 0.f;
        for (int j = lane; j < SV; j += 32) {
            const float e = expf(ss[q * SVP + j] - mx);
            ss[q * SVP + j] = e;
            sum += e;
        }
#pragma unroll
        for (int o = 16; o; o >>= 1)
            sum += __shfl_xor_sync(0xffffffffu, sum, o);
        const float inv = 1.f / sum;
        for (int j = lane; j < SV; j += 32) ss[q * SVP + j] *= inv;
    }
    __syncthreads();

    const int q  = tid >> 3;
    const int dg = tid & 7;
    const int d0 = dg * 36;
    float4 acc[9];
#pragma unroll
    for (int i = 0; i < 9; i++) acc[i] = make_float4(0.f, 0.f, 0.f, 0.f);

    const float* vg = Vm + ((size_t)(b * SV)) * DM + h * DK;
    for (int j0 = 0; j0 < SV; j0 += ATT_KC) {
        const int jn = min(ATT_KC, SV - j0);
        __syncthreads();
        for (int idx = tid; idx < jn * DK; idx += 256) {
            const int r = idx / DK, c = idx - r * DK;
            kv[idx] = vg[(size_t)(j0 + r) * DM + c];
        }
        __syncthreads();
        for (int j = 0; j < jn; j++) {
            const float wgt = ss[q * SVP + j0 + j];
#pragma unroll
            for (int i = 0; i < 9; i++) {
                const float4 vv = *(const float4*)&kv[j * DK + d0 + i * 4];
                acc[i].x += wgt * vv.x;  acc[i].y += wgt * vv.y;
                acc[i].z += wgt * vv.z;  acc[i].w += wgt * vv.w;
            }
        }
    }
    __half2* og = (__half2*)(O + ((size_t)(b * SQ + q0 + q)) * DM + h * DK + d0);
#pragma unroll
    for (int i = 0; i < 9; i++) {
        og[i * 2 + 0] = __floats2half2_rn(acc[i].x, acc[i].y);
        og[i * 2 + 1] = __floats2half2_rn(acc[i].z, acc[i].w);
    }
}

// ---------------------------------------------------------------------------
// Orchestration
// ---------------------------------------------------------------------------
extern "C" void kernel_launch(void* const* d_in, const int* in_sizes, int n_in,
                              void* d_out, int out_size)
{
    const float* vision = (const float*)d_in[0];
    const float* text   = (const float*)d_in[1];
    const float* vp_w   = (const float*)d_in[2];
    const float* vp_b   = (const float*)d_in[3];
    const float* ln1_w  = (const float*)d_in[4];
    const float* ln1_b  = (const float*)d_in[5];
    const float* ln2_w  = (const float*)d_in[6];
    const float* ln2_b  = (const float*)d_in[7];
    const float* wq_w   = (const float*)d_in[8];
    const float* wq_b   = (const float*)d_in[9];
    const float* wk_w   = (const float*)d_in[10];
    const float* wk_b   = (const float*)d_in[11];
    const float* wv_w   = (const float*)d_in[12];
    const float* wv_b   = (const float*)d_in[13];
    const float* wo_w   = (const float*)d_in[14];
    const float* wo_b   = (const float*)d_in[15];
    const float* f1_w   = (const float*)d_in[16];
    const float* f1_b   = (const float*)d_in[17];
    const float* f2_w   = (const float*)d_in[18];
    const float* f2_b   = (const float*)d_in[19];
    float* out = (float*)d_out;

    float *q, *k, *v, *x;
    __half *pv, *nt, *ctx, *h, *vis, *w16;
    cudaGetSymbolAddress((void**)&q,   g_q);
    cudaGetSymbolAddress((void**)&k,   g_k);
    cudaGetSymbolAddress((void**)&v,   g_v);
    cudaGetSymbolAddress((void**)&x,   g_x);
    cudaGetSymbolAddress((void**)&pv,  g_pv);
    cudaGetSymbolAddress((void**)&nt,  g_nt);
    cudaGetSymbolAddress((void**)&ctx, g_ctx);
    cudaGetSymbolAddress((void**)&h,   g_h);
    cudaGetSymbolAddress((void**)&vis, g_vis);
    cudaGetSymbolAddress((void**)&w16, g_w16);

    cudaFuncSetAttribute(hgemm<0,0>, cudaFuncAttributeMaxDynamicSharedMemorySize, GEMM_SMEM);
    cudaFuncSetAttribute(hgemm<0,1>, cudaFuncAttributeMaxDynamicSharedMemorySize, GEMM_SMEM);
    cudaFuncSetAttribute(hgemm<1,0>, cudaFuncAttributeMaxDynamicSharedMemorySize, GEMM_SMEM);
    cudaFuncSetAttribute(hgemm<2,1>, cudaFuncAttributeMaxDynamicSharedMemorySize, GEMM_SMEM);
    cudaFuncSetAttribute(attention_kernel,
                         cudaFuncAttributeMaxDynamicSharedMemorySize, ATT_SMEM);

    const dim3 blk(512);
    const int mtV = (ROWS_V + TM - 1) / TM;   // 17
    const int mtT = ROWS_T / TM;              // 128

    // launches ordered so launch #6 (ncu -s 5 -c 1) is the big Q-proj GEMM
    cvt16_kernel<<<1024, 256>>>(vision, vis, (size_t)ROWS_V * DV);          // 1
    cvt16_kernel<<<1024, 256>>>(vp_w, w16 + OFF_VP, (size_t)DV * DM);       // 2
    hgemm<0,1><<<dim3(DM / TN, mtV), blk, GEMM_SMEM>>>(                     // 3
        vis, w16 + OFF_VP, vp_b, nullptr, pv, ROWS_V, DM, DV);
    layernorm_kernel<<<ROWS_T, 256>>>(text, ln1_w, ln1_b, nt, DM);          // 4
    cvt16_kernel<<<1024, 256>>>(wq_w, w16 + OFF_WQ, (size_t)DM * DM);       // 5
    hgemm<0,0><<<dim3(DM / TN, mtT), blk, GEMM_SMEM>>>(                     // 6 (profiled)
        nt, w16 + OFF_WQ, wq_b, nullptr, q, ROWS_T, DM, DM);
    cvt16_kernel<<<1024, 256>>>(wk_w, w16 + OFF_WK, (size_t)DM * DM);       // 7
    hgemm<0,0><<<dim3(DM / TN, mtV), blk, GEMM_SMEM>>>(                     // 8
        pv, w16 + OFF_WK, wk_b, nullptr, k, ROWS_V, DM, DM);
    cvt16_kernel<<<1024, 256>>>(wv_w, w16 + OFF_WV, (size_t)DM * DM);       // 9
    hgemm<0,0><<<dim3(DM / TN, mtV), blk, GEMM_SMEM>>>(                     // 10
        pv, w16 + OFF_WV, wv_b, nullptr, v, ROWS_V, DM, DM);
    attention_kernel<<<dim3(SQ / ATT_TQ, BATCH * NH), 256, ATT_SMEM>>>(     // 11
        q, k, v, ctx);
    cvt16_kernel<<<1024, 256>>>(wo_w, w16 + OFF_WO, (size_t)DM * DM);       // 12
    hgemm<1,0><<<dim3(DM / TN, mtT), blk, GEMM_SMEM>>>(                     // 13
        ctx, w16 + OFF_WO, wo_b, text, x, ROWS_T, DM, DM);
    layernorm_kernel<<<ROWS_T, 256>>>(x, ln2_w, ln2_b, nt, DM);             // 14
    cvt16_kernel<<<1024, 256>>>(f1_w, w16 + OFF_F1, (size_t)DM * DF);       // 15
    hgemm<2,1><<<dim3(DF / TN, mtT), blk, GEMM_SMEM>>>(                     // 16
        nt, w16 + OFF_F1, f1_b, nullptr, h, ROWS_T, DF, DM);
    cvt16_kernel<<<1024, 256>>>(f2_w, w16 + OFF_F2, (size_t)DF * DM);       // 17
    hgemm<1,0><<<dim3(DM / TN, mtT), blk, GEMM_SMEM>>>(                     // 18
        h, w16 + OFF_F2, f2_b, x, out, ROWS_T, DM, DF);
}

// round 7
// speedup vs baseline: 2.6270x; 1.7739x over previous
#include <cuda_runtime.h>
#include <cuda_fp16.h>
#include <math.h>
#include <cstdint>

// ---------------------------------------------------------------------------
// Problem constants
// ---------------------------------------------------------------------------
#define BATCH 8
#define SV    257
#define SQ    2048
#define DV    1024
#define DM    2304
#define NH    8
#define DK    288
#define DF    9216
#define ROWS_T (BATCH*SQ)  // 16384
#define ROWS_V (BATCH*SV)  // 2056

// ---------------------------------------------------------------------------
// Scratch (device globals; no runtime allocation allowed)
// ---------------------------------------------------------------------------
__device__ float  g_x  [(size_t)ROWS_T * DM];
__device__ __half g_q  [(size_t)ROWS_T * DM];
__device__ __half g_kv [(size_t)ROWS_V * 2 * DM];   // fused [k|v] per row
__device__ __half g_pv [(size_t)ROWS_V * DM];
__device__ __half g_nt [(size_t)ROWS_T * DM];
__device__ __half g_ctx[(size_t)ROWS_T * DM];
__device__ __half g_h  [(size_t)ROWS_T * DF];
__device__ __half g_vis[(size_t)ROWS_V * DV];
__device__ float  g_bkv[2 * DM];
// fp16 weight copies (WK region holds fused [2304 x 4608] kv weight)
#define OFF_VP 0
#define OFF_WQ (OFF_VP + (size_t)DV*DM)
#define OFF_WK (OFF_WQ + (size_t)DM*DM)
#define OFF_WO (OFF_WK + 2*(size_t)DM*DM)
#define OFF_F1 (OFF_WO + (size_t)DM*DM)
#define OFF_F2 (OFF_F1 + (size_t)DM*DF)
#define W16_TOTAL (OFF_F2 + (size_t)DF*DM)
__device__ __half g_w16[W16_TOTAL];

// ---------------------------------------------------------------------------
// helpers
// ---------------------------------------------------------------------------
__device__ __forceinline__ uint32_t smem_u32(const void* p) {
    uint32_t a;
    asm("{ .reg .u64 t; cvta.to.shared.u64 t, %1; cvt.u32.u64 %0, t; }"
        : "=r"(a) : "l"(p));
    return a;
}
__device__ __forceinline__ void cp16(uint32_t dst, const void* src, uint32_t n) {
    asm volatile("cp.async.cg.shared.global [%0], [%1], 16, %2;"
                 :: "r"(dst), "l"(src), "r"(n) : "memory");
}
#define CP_COMMIT() asm volatile("cp.async.commit_group;" ::: "memory")
#define CP_WAIT(N)  asm volatile("cp.async.wait_group %0;" :: "n"(N) : "memory")

__device__ __forceinline__ void ldsm_x4(uint32_t* r, uint32_t addr) {
    asm volatile("ldmatrix.sync.aligned.m8n8.x4.shared.b16 {%0,%1,%2,%3}, [%4];"
        : "=r"(r[0]), "=r"(r[1]), "=r"(r[2]), "=r"(r[3]) : "r"(addr));
}
__device__ __forceinline__ void ldsm_x4_t(uint32_t* r, uint32_t addr) {
    asm volatile("ldmatrix.sync.aligned.m8n8.x4.trans.shared.b16 {%0,%1,%2,%3}, [%4];"
        : "=r"(r[0]), "=r"(r[1]), "=r"(r[2]), "=r"(r[3]) : "r"(addr));
}
__device__ __forceinline__ void mma_f16(float* c, const uint32_t* a,
                                        const uint32_t* b) {
    asm volatile(
        "mma.sync.aligned.m16n8k16.row.col.f32.f16.f16.f32 "
        "{%0,%1,%2,%3}, {%4,%5,%6,%7}, {%8,%9}, {%0,%1,%2,%3};"
        : "+f"(c[0]), "+f"(c[1]), "+f"(c[2]), "+f"(c[3])
        : "r"(a[0]), "r"(a[1]), "r"(a[2]), "r"(a[3]), "r"(b[0]), "r"(b[1]));
}
__device__ __forceinline__ float gelu_exact(float x) {
    return 0.5f * x * (1.0f + erff(x * 0.70710678118654752f));
}

// ---------------------------------------------------------------------------
// conversion kernels
// ---------------------------------------------------------------------------
__global__ void __launch_bounds__(256)
cvt16_kernel(const float* __restrict__ in, __half* __restrict__ out, size_t n)
{
    for (size_t i = (size_t)blockIdx.x * 256 + threadIdx.x; i < n;
         i += (size_t)gridDim.x * 256)
        out[i] = __float2half_rn(in[i]);
}
__global__ void __launch_bounds__(256)
cvt16_cat_kernel(const float* __restrict__ in, __half* __restrict__ out,
                 int rows, int cols, int pitch, int coff)
{
    const size_t n = (size_t)rows * cols;
    for (size_t i = (size_t)blockIdx.x * 256 + threadIdx.x; i < n;
         i += (size_t)gridDim.x * 256) {
        const int r = (int)(i / cols), c = (int)(i - (size_t)r * cols);
        out[(size_t)r * pitch + coff + c] = __float2half_rn(in[i]);
    }
}
__global__ void __launch_bounds__(256)
cat_bias_kernel(const float* __restrict__ a, const float* __restrict__ b,
                float* __restrict__ o, int n)
{
    const int i = blockIdx.x * 256 + threadIdx.x;
    if (i < 2 * n) o[i] = (i < n) ? a[i] : b[i - n];
}

// ---------------------------------------------------------------------------
// fp16 HMMA GEMM: C[M,N] = A[M,K] @ B[K,N] + bias (+ epilogue)
//   EPI 0: +bias   EPI 1: +bias+res   EPI 2: gelu(+bias)
//   OUT16: write __half output, else float.
// CTA tile 128x256, KC=64, 3-stage cp.async, 512 thr, 16 warps x (64x32).
// Requires: K % 64 == 0, N % 256 == 0, K/64 >= 2. M tail handled.
// ---------------------------------------------------------------------------
#define TM 128
#define TN 256
#define KC 64
#define NSTG 3
#define A_ROWB 144                     // 128B data + 16B pad
#define A_BYTES (128 * A_ROWB)         // 18432
#define B_BYTES (KC * 512)             // 32768
#define STG_BYTES (A_BYTES + B_BYTES)  // 51200
#define GEMM_SMEM (NSTG * STG_BYTES)   // 153600

__device__ __forceinline__ void load_stage(
    const __half* __restrict__ A, const __half* __restrict__ Bw,
    int M, int N, int K, uint32_t stg, int bm, int n0, int kc, int tid)
{
#pragma unroll
    for (int i = 0; i < 2; i++) {   // A: 1024 cp16
        const int ai = tid + i * 512;
        const int row = ai >> 3, c = ai & 7;
        const int gr = bm + row;
        const int ok = gr < M;
        cp16(stg + row * A_ROWB + c * 16,
             A + (size_t)(ok ? gr : 0) * K + kc + c * 8, ok ? 16u : 0u);
    }
#pragma unroll
    for (int i = 0; i < 4; i++) {   // B: 2048 cp16
        const int bi = tid + i * 512;
        const int k = bi >> 5, cc = bi & 31;
        cp16(stg + A_BYTES + k * 512 + ((cc ^ (k & 7)) << 4),
             Bw + (size_t)(kc + k) * N + n0 + cc * 8, 16u);
    }
}

template <int EPI, int OUT16>
__global__ void __launch_bounds__(512, 1)
hgemm(const __half* __restrict__ A, const __half* __restrict__ Bw,
      const float* __restrict__ bias, const float* __restrict__ res,
      void* __restrict__ Cv, int M, int N, int K)
{
    extern __shared__ char smem[];
    const uint32_t sb = smem_u32(smem);
    const int tid  = threadIdx.x;
    const int lane = tid & 31;
    const int wid  = tid >> 5;
    const int wm   = (wid >> 3) * 64;
    const int wn   = (wid & 7) * 32;
    const int bm   = blockIdx.y * TM;
    const int n0   = blockIdx.x * TN;
    const int nch  = K / KC;

    float c[4][4][4];
#pragma unroll
    for (int mt = 0; mt < 4; mt++)
#pragma unroll
        for (int nt = 0; nt < 4; nt++)
#pragma unroll
            for (int r = 0; r < 4; r++) c[mt][nt][r] = 0.f;

    load_stage(A, Bw, M, N, K, sb, bm, n0, 0, tid);
    CP_COMMIT();
    load_stage(A, Bw, M, N, K, sb + STG_BYTES, bm, n0, KC, tid);
    CP_COMMIT();

    const int la_row = wm + (lane & 15);
    const int la_chk = lane >> 4;
    const int lb_k   = lane & 15;
    const int lb_chk = (wn >> 3) + (lane >> 4);

    for (int chunk = 0; chunk < nch; ++chunk) {
        CP_WAIT(1);
        __syncthreads();

        const int nx = chunk + 2;
        if (nx < nch)
            load_stage(A, Bw, M, N, K, sb + (nx % NSTG) * STG_BYTES,
                       bm, n0, nx * KC, tid);
        CP_COMMIT();

        const uint32_t stgA = sb + (chunk % NSTG) * STG_BYTES;
        const uint32_t stgB = stgA + A_BYTES;

#pragma unroll
        for (int kk = 0; kk < 4; kk++) {
            uint32_t a[4][4], bfr[2][4];
#pragma unroll
            for (int mt = 0; mt < 4; mt++)
                ldsm_x4(a[mt], stgA + (la_row + mt * 16) * A_ROWB +
                               (kk * 2 + la_chk) * 16);
            {
                const int k = kk * 16 + lb_k;
                const uint32_t krow = stgB + k * 512;
                const int swk = k & 7;
                ldsm_x4_t(bfr[0], krow + (((lb_chk    ) ^ swk) << 4));
                ldsm_x4_t(bfr[1], krow + (((lb_chk + 2) ^ swk) << 4));
            }
#pragma unroll
            for (int mt = 0; mt < 4; mt++)
#pragma unroll
                for (int nt = 0; nt < 4; nt++)
                    mma_f16(c[mt][nt], a[mt], &bfr[nt >> 1][(nt & 1) * 2]);
        }
    }

    // -------- epilogue --------
    const int l4 = lane >> 2;
    const int lk = lane & 3;
#pragma unroll
    for (int mt = 0; mt < 4; mt++) {
        const int rb = bm + wm + mt * 16 + l4;
#pragma unroll
        for (int hh = 0; hh < 2; hh++) {
            const int row = rb + hh * 8;
            if (row < M) {
#pragma unroll
                for (int nt = 0; nt < 4; nt++) {
                    const int col = n0 + wn + nt * 8 + lk * 2;
                    float v0 = c[mt][nt][hh * 2 + 0] + bias[col];
                    float v1 = c[mt][nt][hh * 2 + 1] + bias[col + 1];
                    if (EPI == 1) {
                        const float2 r2 = *(const float2*)&res[(size_t)row * N + col];
                        v0 += r2.x; v1 += r2.y;
                    } else if (EPI == 2) {
                        v0 = gelu_exact(v0); v1 = gelu_exact(v1);
                    }
                    if (OUT16) {
                        __half2* C = (__half2*)Cv;
                        C[((size_t)row * N + col) >> 1] =
                            __floats2half2_rn(v0, v1);
                    } else {
                        float* C = (float*)Cv;
                        *(float2*)&C[(size_t)row * N + col] = make_float2(v0, v1);
                    }
                }
            }
        }
    }
}

// ---------------------------------------------------------------------------
// LayerNorm over last dim (C = DM), one block per row; fp16 output.
// ---------------------------------------------------------------------------
__global__ void __launch_bounds__(256)
layernorm_kernel(const float* __restrict__ x, const float* __restrict__ w,
                 const float* __restrict__ bta, __half* __restrict__ y, int C)
{
    const size_t base = (size_t)blockIdx.x * C;
    float s = 0.f, s2 = 0.f;
    for (int c = threadIdx.x; c < C; c += 256) {
        const float v = x[base + c];
        s += v; s2 += v * v;
    }
#pragma unroll
    for (int o = 16; o; o >>= 1) {
        s  += __shfl_xor_sync(0xffffffffu, s,  o);
        s2 += __shfl_xor_sync(0xffffffffu, s2, o);
    }
    __shared__ float sh[16];
    __shared__ float mv[2];
    const int wid = threadIdx.x >> 5, lane = threadIdx.x & 31;
    if (lane == 0) { sh[wid] = s; sh[8 + wid] = s2; }
    __syncthreads();
    if (threadIdx.x == 0) {
        float ts = 0.f, ts2 = 0.f;
#pragma unroll
        for (int i = 0; i < 8; i++) { ts += sh[i]; ts2 += sh[8 + i]; }
        const float mean = ts / (float)C;
        const float var  = ts2 / (float)C - mean * mean;
        mv[0] = mean;
        mv[1] = rsqrtf(var + 1e-5f);
    }
    __syncthreads();
    const float mean = mv[0], rstd = mv[1];
    for (int c = threadIdx.x; c < C; c += 256)
        y[base + c] = __float2half_rn((x[base + c] - mean) * rstd * w[c] + bta[c]);
}

// ---------------------------------------------------------------------------
// Tensor-core cross attention.
// Per block: (b, h, 64 q-rows). Two passes with 32-row KV chunks, ping-pong
// cp.async. Scores fp32 in smem, softmax, attn->fp16, ctx fp32 accum.
// ---------------------------------------------------------------------------
#define ATQ 64
#define ACH 32
#define ANCH 10            // 320 padded kv columns
#define ASS 320
#define ASS_STR 328        // floats
#define AQR 592            // bytes per q/kv smem row (288 halfs + pad)
#define AHR 656            // bytes per ah smem row (328 halfs)
#define QS_BYTES (ATQ * AQR)            // 37888
#define KVB      (ACH * AQR)            // 18944
#define SS_BYTES (ATQ * ASS_STR * 4)    // 83968
#define AH_BYTES (ATQ * AHR)            // 41984
#define AT_SMEM  (QS_BYTES + 2*KVB + SS_BYTES + AH_BYTES)   // 201728

__device__ __forceinline__ void att_load_kv(const __half* base, int c,
                                            uint32_t buf, int tid)
{
#pragma unroll
    for (int i = 0; i < 5; i++) {
        const int idx = tid + i * 256;
        if (idx < ACH * 36) {
            const int r = idx / 36, cc = idx - r * 36;
            const int kr = c * ACH + r;
            const int ok = kr < SV;
            cp16(buf + r * AQR + cc * 16,
                 base + (size_t)(ok ? kr : 0) * (2 * DM) + cc * 8,
                 ok ? 16u : 0u);
        }
    }
    CP_COMMIT();
}

__global__ void __launch_bounds__(256, 1)
attention_kernel(const __half* __restrict__ Q, const __half* __restrict__ KV,
                 __half* __restrict__ O)
{
    extern __shared__ char smem[];
    const uint32_t sb  = smem_u32(smem);
    const uint32_t qsb = sb;
    const uint32_t kvb = sb + QS_BYTES;
    float*  ss = (float*)(smem + QS_BYTES + 2 * KVB);
    __half* ah = (__half*)(smem + QS_BYTES + 2 * KVB + SS_BYTES);
    const uint32_t ahb = kvb + 2 * KVB + SS_BYTES;

    const int q0   = blockIdx.x * ATQ;
    const int b    = blockIdx.y >> 3;
    const int h    = blockIdx.y & 7;
    const int tid  = threadIdx.x;
    const int lane = tid & 31;
    const int w    = tid >> 5;
    const float scale = 0.05892556509887896f;   // 1/sqrt(288)

    // ---- Q tile load (group 0) ----
    const __half* qg = Q + ((size_t)(b * SQ + q0)) * DM + h * DK;
#pragma unroll
    for (int i = 0; i < 9; i++) {
        const int idx = tid + i * 256;
        const int r = idx / 36, cc = idx - r * 36;
        cp16(qsb + r * AQR + cc * 16, qg + (size_t)r * DM + cc * 8, 16u);
    }
    CP_COMMIT();

    const __half* kg = KV + ((size_t)(b * SV)) * (2 * DM) + h * DK;
    const __half* vg = kg + DM;

    att_load_kv(kg, 0, kvb, tid);
    att_load_kv(kg, 1, kvb + KVB, tid);

    CP_WAIT(1);                 // Q + K0 done
    __syncthreads();

    // ---- hoist Q fragments: warp m-tile m1, 18 k-steps ----
    const int m1 = (w & 3) * 16;
    const int n1 = (w >> 2) * 16;      // within-chunk n base (0 or 16)
    uint32_t qf[18][4];
    {
        const uint32_t abase = qsb + (m1 + (lane & 15)) * AQR + (lane >> 4) * 16;
#pragma unroll
        for (int ks = 0; ks < 18; ks++)
            ldsm_x4(qf[ks], abase + ks * 32);
    }

    const int l4 = lane >> 2, lk = lane & 3;

    // ================= pass 1: scores =================
    for (int c = 0; c < ANCH; c++) {
        if (c > 0) { CP_WAIT(1); __syncthreads(); }
        const uint32_t kb = kvb + (c & 1) * KVB;
        float sc[2][4];
#pragma unroll
        for (int nt = 0; nt < 2; nt++)
#pragma unroll
            for (int r = 0; r < 4; r++) sc[nt][r] = 0.f;

        const uint32_t bbase = kb + (n1 + (lane & 15)) * AQR + (lane >> 4) * 16;
#pragma unroll
        for (int ks = 0; ks < 18; ks++) {
            uint32_t bf[4];
            ldsm_x4(bf, bbase + ks * 32);
            uint32_t b0[2] = { bf[0], bf[2] };
            uint32_t b1[2] = { bf[1], bf[3] };
            mma_f16(sc[0], qf[ks], b0);
            mma_f16(sc[1], qf[ks], b1);
        }
#pragma unroll
        for (int nt = 0; nt < 2; nt++) {
            const int col = c * ACH + n1 + nt * 8 + lk * 2;
#pragma unroll
            for (int hh = 0; hh < 2; hh++) {
                const int row = m1 + l4 + hh * 8;
                const float v0 = sc[nt][hh * 2 + 0] * scale;
                const float v1 = sc[nt][hh * 2 + 1] * scale;
                ss[row * ASS_STR + col]     = (col     < SV) ? v0 : -1e30f;
                ss[row * ASS_STR + col + 1] = (col + 1 < SV) ? v1 : -1e30f;
            }
        }
        __syncthreads();
        if (c + 2 < ANCH) att_load_kv(kg, c + 2, kb, tid);
        else CP_COMMIT();
    }

    // issue V0/V1 while softmax runs
    att_load_kv(vg, 0, kvb, tid);
    att_load_kv(vg, 1, kvb + KVB, tid);

    // ================= softmax (warp-private rows) =================
#pragma unroll
    for (int i = 0; i < 8; i++) {
        const int r = w * 8 + i;
        float mx = -1e30f;
#pragma unroll
        for (int j = 0; j < 10; j++)
            mx = fmaxf(mx, ss[r * ASS_STR + lane + j * 32]);
#pragma unroll
        for (int o = 16; o; o >>= 1)
            mx = fmaxf(mx, __shfl_xor_sync(0xffffffffu, mx, o));
        float sum = 0.f;
        float ev[10];
#pragma unroll
        for (int j = 0; j < 10; j++) {
            ev[j] = expf(ss[r * ASS_STR + lane + j * 32] - mx);
            sum += ev[j];
        }
#pragma unroll
        for (int o = 16; o; o >>= 1)
            sum += __shfl_xor_sync(0xffffffffu, sum, o);
        const float inv = 1.f / sum;
#pragma unroll
        for (int j = 0; j < 10; j++)
            ah[r * (AHR / 2) + lane + j * 32] = __float2half_rn(ev[j] * inv);
    }

    // ================= pass 2: ctx = attn @ V =================
    const int m2  = (w & 1) * 32;
    const int n0w = (w >> 1) * 72;
    float ctx[2][9][4];
#pragma unroll
    for (int mt = 0; mt < 2; mt++)
#pragma unroll
        for (int nt = 0; nt < 9; nt++)
#pragma unroll
            for (int r = 0; r < 4; r++) ctx[mt][nt][r] = 0.f;

    for (int c = 0; c < ANCH; c++) {
        CP_WAIT(1);
        __syncthreads();
        const uint32_t vb = kvb + (c & 1) * KVB;

        uint32_t af[2][2][4];
#pragma unroll
        for (int mt = 0; mt < 2; mt++) {
            const uint32_t abase = ahb + (m2 + mt * 16 + (lane & 15)) * AHR +
                                   (lane >> 4) * 16;
            ldsm_x4(af[mt][0], abase + (2 * c) * 32);
            ldsm_x4(af[mt][1], abase + (2 * c) * 32 + 32);
        }
#pragma unroll
        for (int kk = 0; kk < 2; kk++) {
#pragma unroll
            for (int p = 0; p < 5; p++) {
                uint32_t bf[4];
                const uint32_t baddr = vb + (kk * 16 + (lane & 15)) * AQR +
                                       (n0w + p * 16 + (lane >> 4) * 8) * 2;
                ldsm_x4_t(bf, baddr);
#pragma unroll
                for (int mt = 0; mt < 2; mt++) {
                    mma_f16(ctx[mt][2 * p], af[mt][kk], &bf[0]);
                    if (2 * p + 1 < 9)
                        mma_f16(ctx[mt][2 * p + 1], af[mt][kk], &bf[2]);
                }
            }
        }
        __syncthreads();
        if (c + 2 < ANCH) att_load_kv(vg, c + 2, vb, tid);
        else CP_COMMIT();
    }

    // ---- write ctx ----
#pragma unroll
    for (int mt = 0; mt < 2; mt++) {
#pragma unroll
        for (int hh = 0; hh < 2; hh++) {
            const int row = m2 + mt * 16 + l4 + hh * 8;
            __half* og = O + ((size_t)(b * SQ + q0 + row)) * DM + h * DK;
#pragma unroll
            for (int nt = 0; nt < 9; nt++) {
                const int col = n0w + nt * 8 + lk * 2;
                *(__half2*)(og + col) =
                    __floats2half2_rn(ctx[mt][nt][hh * 2 + 0],
                                      ctx[mt][nt][hh * 2 + 1]);
            }
        }
    }
}

// ---------------------------------------------------------------------------
// Orchestration
// ---------------------------------------------------------------------------
extern "C" void kernel_launch(void* const* d_in, const int* in_sizes, int n_in,
                              void* d_out, int out_size)
{
    const float* vision = (const float*)d_in[0];
    const float* text   = (const float*)d_in[1];
    const float* vp_w   = (const float*)d_in[2];
    const float* vp_b   = (const float*)d_in[3];
    const float* ln1_w  = (const float*)d_in[4];
    const float* ln1_b  = (const float*)d_in[5];
    const float* ln2_w  = (const float*)d_in[6];
    const float* ln2_b  = (const float*)d_in[7];
    const float* wq_w   = (const float*)d_in[8];
    const float* wq_b   = (const float*)d_in[9];
    const float* wk_w   = (const float*)d_in[10];
    const float* wk_b   = (const float*)d_in[11];
    const float* wv_w   = (const float*)d_in[12];
    const float* wv_b   = (const float*)d_in[13];
    const float* wo_w   = (const float*)d_in[14];
    const float* wo_b   = (const float*)d_in[15];
    const float* f1_w   = (const float*)d_in[16];
    const float* f1_b   = (const float*)d_in[17];
    const float* f2_w   = (const float*)d_in[18];
    const float* f2_b   = (const float*)d_in[19];
    float* out = (float*)d_out;

    float *x, *bkv;
    __half *q, *kv, *pv, *nt, *ctx, *h, *vis, *w16;
    cudaGetSymbolAddress((void**)&x,   g_x);
    cudaGetSymbolAddress((void**)&q,   g_q);
    cudaGetSymbolAddress((void**)&kv,  g_kv);
    cudaGetSymbolAddress((void**)&pv,  g_pv);
    cudaGetSymbolAddress((void**)&nt,  g_nt);
    cudaGetSymbolAddress((void**)&ctx, g_ctx);
    cudaGetSymbolAddress((void**)&h,   g_h);
    cudaGetSymbolAddress((void**)&vis, g_vis);
    cudaGetSymbolAddress((void**)&w16, g_w16);
    cudaGetSymbolAddress((void**)&bkv, g_bkv);

    cudaFuncSetAttribute(hgemm<0,1>, cudaFuncAttributeMaxDynamicSharedMemorySize, GEMM_SMEM);
    cudaFuncSetAttribute(hgemm<1,0>, cudaFuncAttributeMaxDynamicSharedMemorySize, GEMM_SMEM);
    cudaFuncSetAttribute(hgemm<2,1>, cudaFuncAttributeMaxDynamicSharedMemorySize, GEMM_SMEM);
    cudaFuncSetAttribute(attention_kernel,
                         cudaFuncAttributeMaxDynamicSharedMemorySize, AT_SMEM);

    const dim3 blk(512);
    const int mtV = (ROWS_V + TM - 1) / TM;   // 17
    const int mtT = ROWS_T / TM;              // 128

    cvt16_kernel<<<1024, 256>>>(vision, vis, (size_t)ROWS_V * DV);
    cvt16_kernel<<<1024, 256>>>(vp_w, w16 + OFF_VP, (size_t)DV * DM);
    hgemm<0,1><<<dim3(DM / TN, mtV), blk, GEMM_SMEM>>>(
        vis, w16 + OFF_VP, vp_b, nullptr, pv, ROWS_V, DM, DV);
    layernorm_kernel<<<ROWS_T, 256>>>(text, ln1_w, ln1_b, nt, DM);
    cvt16_kernel<<<1024, 256>>>(wq_w, w16 + OFF_WQ, (size_t)DM * DM);
    hgemm<0,1><<<dim3(DM / TN, mtT), blk, GEMM_SMEM>>>(
        nt, w16 + OFF_WQ, wq_b, nullptr, q, ROWS_T, DM, DM);
    cvt16_cat_kernel<<<1024, 256>>>(wk_w, w16 + OFF_WK, DM, DM, 2 * DM, 0);
    cvt16_cat_kernel<<<1024, 256>>>(wv_w, w16 + OFF_WK, DM, DM, 2 * DM, DM);
    cat_bias_kernel<<<(2 * DM + 255) / 256, 256>>>(wk_b, wv_b, bkv, DM);
    hgemm<0,1><<<dim3((2 * DM) / TN, mtV), blk, GEMM_SMEM>>>(
        pv, w16 + OFF_WK, bkv, nullptr, kv, ROWS_V, 2 * DM, DM);
    attention_kernel<<<dim3(SQ / ATQ, BATCH * NH), 256, AT_SMEM>>>(q, kv, ctx);
    cvt16_kernel<<<1024, 256>>>(wo_w, w16 + OFF_WO, (size_t)DM * DM);
    hgemm<1,0><<<dim3(DM / TN, mtT), blk, GEMM_SMEM>>>(
        ctx, w16 + OFF_WO, wo_b, text, x, ROWS_T, DM, DM);
    layernorm_kernel<<<ROWS_T, 256>>>(x, ln2_w, ln2_b, nt, DM);
    cvt16_kernel<<<1024, 256>>>(f1_w, w16 + OFF_F1, (size_t)DM * DF);
    hgemm<2,1><<<dim3(DF / TN, mtT), blk, GEMM_SMEM>>>(
        nt, w16 + OFF_F1, f1_b, nullptr, h, ROWS_T, DF, DM);
    cvt16_kernel<<<1024, 256>>>(f2_w, w16 + OFF_F2, (size_t)DF * DM);
    hgemm<1,0><<<dim3(DM / TN, mtT), blk, GEMM_SMEM>>>(
        h, w16 + OFF_F2, f2_b, x, out, ROWS_T, DM, DF);
}